// round 1
// baseline (speedup 1.0000x reference)
#include <cuda_runtime.h>
#include <math.h>

#define SEQ 4096
#define HID 2048
#define NH  16
#define HD  128

// ---------------- scratch (device globals; no allocation allowed) ----------
__device__ float g_q[SEQ * HID];
__device__ float g_k[SEQ * HID];
__device__ float g_v[SEQ * HID];
__device__ float g_ctx[SEQ * HID];

// ---------------- fp32 SGEMM: C[M,N] = A[M,K] * B[K,N] ---------------------
// 128x128 block tile, BK=8, 256 threads, 8x8 per thread.
__global__ __launch_bounds__(256) void sgemm128(const float* __restrict__ A,
                                                const float* __restrict__ B,
                                                float* __restrict__ C,
                                                int M, int N, int K)
{
    __shared__ float As[8][128];
    __shared__ float Bs[8][128];

    const int tid = threadIdx.x;
    const int tx  = tid & 15;
    const int ty  = tid >> 4;
    const int bx  = blockIdx.x * 128;
    const int by  = blockIdx.y * 128;

    const int aRow = tid >> 1;         // 0..127
    const int aCol = (tid & 1) * 4;    // 0 or 4
    const int bRow = tid >> 5;         // 0..7
    const int bCol = (tid & 31) * 4;   // 0..124

    const float* Ap = A + (long)(by + aRow) * K + aCol;
    const float* Bp = B + (long)bRow * N + bx + bCol;

    float acc[8][8] = {};

    for (int k0 = 0; k0 < K; k0 += 8) {
        float4 a4 = *(const float4*)(Ap + k0);
        float4 b4 = *(const float4*)(Bp + (long)k0 * N);
        As[aCol + 0][aRow] = a4.x;
        As[aCol + 1][aRow] = a4.y;
        As[aCol + 2][aRow] = a4.z;
        As[aCol + 3][aRow] = a4.w;
        *(float4*)&Bs[bRow][bCol] = b4;
        __syncthreads();

#pragma unroll
        for (int k = 0; k < 8; k++) {
            float4 a0 = *(float4*)&As[k][ty * 8];
            float4 a1 = *(float4*)&As[k][ty * 8 + 4];
            float4 b0 = *(float4*)&Bs[k][tx * 8];
            float4 b1 = *(float4*)&Bs[k][tx * 8 + 4];
            float ar[8] = {a0.x, a0.y, a0.z, a0.w, a1.x, a1.y, a1.z, a1.w};
            float br[8] = {b0.x, b0.y, b0.z, b0.w, b1.x, b1.y, b1.z, b1.w};
#pragma unroll
            for (int i = 0; i < 8; i++)
#pragma unroll
                for (int j = 0; j < 8; j++)
                    acc[i][j] = fmaf(ar[i], br[j], acc[i][j]);
        }
        __syncthreads();
    }

#pragma unroll
    for (int i = 0; i < 8; i++) {
        float* cp = C + (long)(by + ty * 8 + i) * N + bx + tx * 8;
        float4 o0 = make_float4(acc[i][0], acc[i][1], acc[i][2], acc[i][3]);
        float4 o1 = make_float4(acc[i][4], acc[i][5], acc[i][6], acc[i][7]);
        *(float4*)cp       = o0;
        *(float4*)(cp + 4) = o1;
    }
}

// ---------------- fused per-head RMSNorm + RoPE (in place, Q and K) --------
// grid = SEQ blocks, 256 threads (8 warps). One warp handles one head's
// 128 elems (4 per lane), looping h += 8.
__global__ __launch_bounds__(256) void rms_rope(float* __restrict__ q,
                                                float* __restrict__ k,
                                                const int* __restrict__ pos,
                                                const float* __restrict__ qw,
                                                const float* __restrict__ kw)
{
    const int s    = blockIdx.x;
    const int warp = threadIdx.x >> 5;
    const int lane = threadIdx.x & 31;
    const float p  = (float)pos[s];

    const int d   = lane * 4;       // element offset within head
    const int dp0 = lane * 2;       // rope pair index of first pair
    // freq_i = 10000^(-i/64) = exp(-i * ln(10000)/64)
    const float Cf = 9.210340371976184f / 64.0f;
    float f0 = __expf(-(float)dp0 * Cf);
    float f1 = __expf(-(float)(dp0 + 1) * Cf);
    float s0, c0, s1, c1;
    sincosf(p * f0, &s0, &c0);
    sincosf(p * f1, &s1, &c1);

    float4 w_q = *(const float4*)(qw + d);
    float4 w_k = *(const float4*)(kw + d);

    for (int h = warp; h < NH; h += 8) {
        float* base_q = q + ((long)s * NH + h) * HD + d;
        float* base_k = k + ((long)s * NH + h) * HD + d;
#pragma unroll
        for (int which = 0; which < 2; which++) {
            float* ptr = which ? base_k : base_q;
            float4 wv  = which ? w_k : w_q;
            float4 x = *(float4*)ptr;
            float ss = x.x * x.x + x.y * x.y + x.z * x.z + x.w * x.w;
#pragma unroll
            for (int off = 16; off; off >>= 1)
                ss += __shfl_xor_sync(0xffffffffu, ss, off);
            float r = rsqrtf(ss * (1.0f / 128.0f) + 1e-6f);
            x.x *= r * wv.x; x.y *= r * wv.y; x.z *= r * wv.z; x.w *= r * wv.w;
            float o0 = x.x * c0 - x.y * s0;
            float o1 = x.x * s0 + x.y * c0;
            float o2 = x.z * c1 - x.w * s1;
            float o3 = x.z * s1 + x.w * c1;
            *(float4*)ptr = make_float4(o0, o1, o2, o3);
        }
    }
}

// ---------------- flash attention (fp32, non-causal) -----------------------
// grid = (SEQ/64, NH), 256 threads. Q tile 64x128 (pre-scaled), KV tiles
// 64x128, P staged in smem. Thread (tx,ty): scores 4q x 4k, acc 4q x 8d.
#define QSTR 132
#define PSTR 68
#define FLASH_SMEM ((3 * 64 * QSTR + 64 * PSTR) * 4)

__global__ __launch_bounds__(256) void flash_attn(const float* __restrict__ Q,
                                                  const float* __restrict__ K,
                                                  const float* __restrict__ V,
                                                  float* __restrict__ O)
{
    extern __shared__ float sm[];
    float* Qs = sm;                  // 64 x 132
    float* Ks = Qs + 64 * QSTR;      // 64 x 132
    float* Vs = Ks + 64 * QSTR;      // 64 x 132
    float* Ps = Vs + 64 * QSTR;      // 64 x 68

    const int tid = threadIdx.x;
    const int tx  = tid & 15;
    const int ty  = tid >> 4;
    const int h   = blockIdx.y;
    const int q0  = blockIdx.x * 64;
    const float scale = 0.08838834764831845f;   // 1/sqrt(128)

    // load + pre-scale Q tile
    for (int v = tid; v < 64 * 32; v += 256) {
        int r = v >> 5, c = (v & 31) * 4;
        float4 x = *(const float4*)(Q + ((long)(q0 + r) * NH + h) * HD + c);
        x.x *= scale; x.y *= scale; x.z *= scale; x.w *= scale;
        *(float4*)&Qs[r * QSTR + c] = x;
    }

    float acc[4][8] = {};
    float mi[4] = {-1e30f, -1e30f, -1e30f, -1e30f};
    float li[4] = {};

    for (int kt = 0; kt < SEQ; kt += 64) {
        __syncthreads();   // KV/P buffers free from previous iteration
        for (int v = tid; v < 64 * 32; v += 256) {
            int r = v >> 5, c = (v & 31) * 4;
            *(float4*)&Ks[r * QSTR + c] =
                *(const float4*)(K + ((long)(kt + r) * NH + h) * HD + c);
            *(float4*)&Vs[r * QSTR + c] =
                *(const float4*)(V + ((long)(kt + r) * NH + h) * HD + c);
        }
        __syncthreads();

        // ---- scores: s[i][j] = sum_d Qs[ty*4+i][d] * Ks[tx*4+j][d]
        float sc[4][4] = {};
#pragma unroll 4
        for (int d = 0; d < HD; d += 4) {
            float4 q4[4], k4[4];
#pragma unroll
            for (int i = 0; i < 4; i++)
                q4[i] = *(float4*)&Qs[(ty * 4 + i) * QSTR + d];
#pragma unroll
            for (int j = 0; j < 4; j++)
                k4[j] = *(float4*)&Ks[(tx * 4 + j) * QSTR + d];
#pragma unroll
            for (int i = 0; i < 4; i++)
#pragma unroll
                for (int j = 0; j < 4; j++) {
                    sc[i][j] = fmaf(q4[i].x, k4[j].x, sc[i][j]);
                    sc[i][j] = fmaf(q4[i].y, k4[j].y, sc[i][j]);
                    sc[i][j] = fmaf(q4[i].z, k4[j].z, sc[i][j]);
                    sc[i][j] = fmaf(q4[i].w, k4[j].w, sc[i][j]);
                }
        }

        // ---- online softmax update
        float mnew[4], alpha[4];
#pragma unroll
        for (int i = 0; i < 4; i++) {
            float rm = fmaxf(fmaxf(sc[i][0], sc[i][1]), fmaxf(sc[i][2], sc[i][3]));
#pragma unroll
            for (int off = 8; off; off >>= 1)
                rm = fmaxf(rm, __shfl_xor_sync(0xffffffffu, rm, off));
            mnew[i]  = fmaxf(mi[i], rm);
            alpha[i] = __expf(mi[i] - mnew[i]);
            mi[i]    = mnew[i];
        }
#pragma unroll
        for (int i = 0; i < 4; i++) {
            float rs = 0.f;
#pragma unroll
            for (int j = 0; j < 4; j++) {
                float pv = __expf(sc[i][j] - mnew[i]);
                Ps[(ty * 4 + i) * PSTR + tx * 4 + j] = pv;
                rs += pv;
            }
#pragma unroll
            for (int off = 8; off; off >>= 1)
                rs += __shfl_xor_sync(0xffffffffu, rs, off);
            li[i] = li[i] * alpha[i] + rs;
#pragma unroll
            for (int jd = 0; jd < 8; jd++) acc[i][jd] *= alpha[i];
        }
        __syncthreads();

        // ---- acc += P * V   (thread covers d-cols tx*8..tx*8+7)
#pragma unroll 4
        for (int kc = 0; kc < 64; kc++) {
            float pr[4];
#pragma unroll
            for (int i = 0; i < 4; i++) pr[i] = Ps[(ty * 4 + i) * PSTR + kc];
            float4 v0 = *(float4*)&Vs[kc * QSTR + tx * 8];
            float4 v1 = *(float4*)&Vs[kc * QSTR + tx * 8 + 4];
#pragma unroll
            for (int i = 0; i < 4; i++) {
                acc[i][0] = fmaf(pr[i], v0.x, acc[i][0]);
                acc[i][1] = fmaf(pr[i], v0.y, acc[i][1]);
                acc[i][2] = fmaf(pr[i], v0.z, acc[i][2]);
                acc[i][3] = fmaf(pr[i], v0.w, acc[i][3]);
                acc[i][4] = fmaf(pr[i], v1.x, acc[i][4]);
                acc[i][5] = fmaf(pr[i], v1.y, acc[i][5]);
                acc[i][6] = fmaf(pr[i], v1.z, acc[i][6]);
                acc[i][7] = fmaf(pr[i], v1.w, acc[i][7]);
            }
        }
    }

    // ---- epilogue: normalize and write context [s][h][d]
#pragma unroll
    for (int i = 0; i < 4; i++) {
        float inv = 1.0f / li[i];
        int row = q0 + ty * 4 + i;
        float* op = O + ((long)row * NH + h) * HD + tx * 8;
        float4 o0 = make_float4(acc[i][0] * inv, acc[i][1] * inv,
                                acc[i][2] * inv, acc[i][3] * inv);
        float4 o1 = make_float4(acc[i][4] * inv, acc[i][5] * inv,
                                acc[i][6] * inv, acc[i][7] * inv);
        *(float4*)op       = o0;
        *(float4*)(op + 4) = o1;
    }
}

// ---------------- launch ---------------------------------------------------
extern "C" void kernel_launch(void* const* d_in, const int* in_sizes, int n_in,
                              void* d_out, int out_size)
{
    const float* x   = (const float*)d_in[0];
    const int*   pos = (const int*)d_in[1];
    const float* wq  = (const float*)d_in[2];
    const float* wk  = (const float*)d_in[3];
    const float* wv  = (const float*)d_in[4];
    const float* wo  = (const float*)d_in[5];
    const float* qnw = (const float*)d_in[6];
    const float* knw = (const float*)d_in[7];
    float* out = (float*)d_out;

    float *q, *k, *v, *ctx;
    cudaGetSymbolAddress((void**)&q,   g_q);
    cudaGetSymbolAddress((void**)&k,   g_k);
    cudaGetSymbolAddress((void**)&v,   g_v);
    cudaGetSymbolAddress((void**)&ctx, g_ctx);

    cudaFuncSetAttribute(flash_attn,
                         cudaFuncAttributeMaxDynamicSharedMemorySize,
                         FLASH_SMEM);

    dim3 gemm_grid(HID / 128, SEQ / 128);
    sgemm128<<<gemm_grid, 256>>>(x, wq, q, SEQ, HID, HID);
    sgemm128<<<gemm_grid, 256>>>(x, wk, k, SEQ, HID, HID);
    sgemm128<<<gemm_grid, 256>>>(x, wv, v, SEQ, HID, HID);

    rms_rope<<<SEQ, 256>>>(q, k, pos, qnw, knw);

    flash_attn<<<dim3(SEQ / 64, NH), 256, FLASH_SMEM>>>(q, k, v, ctx);

    sgemm128<<<gemm_grid, 256>>>(ctx, wo, out, SEQ, HID, HID);
}

// round 2
// speedup vs baseline: 1.0707x; 1.0707x over previous
#include <cuda_runtime.h>
#include <stdint.h>
#include <math.h>

#define SEQ 4096
#define HID 2048
#define NH  16
#define HD  128

// ---------------- scratch (device globals; no allocation allowed) ----------
__device__ float g_q[SEQ * HID];
__device__ float g_k[SEQ * HID];
__device__ float g_v[SEQ * HID];
__device__ float g_ctx[SEQ * HID];

// ---------------- tf32 helpers ---------------------------------------------
__device__ __forceinline__ float to_tf32(float x) {
    uint32_t u;
    asm("cvt.rna.tf32.f32 %0, %1;" : "=r"(u) : "f"(x));
    return __uint_as_float(u);
}

__device__ __forceinline__ void mma_tf32(float d[4], const uint32_t a[4],
                                         const uint32_t b[2]) {
    asm volatile(
        "mma.sync.aligned.m16n8k8.row.col.f32.tf32.tf32.f32 "
        "{%0,%1,%2,%3}, {%4,%5,%6,%7}, {%8,%9}, {%0,%1,%2,%3};"
        : "+f"(d[0]), "+f"(d[1]), "+f"(d[2]), "+f"(d[3])
        : "r"(a[0]), "r"(a[1]), "r"(a[2]), "r"(a[3]), "r"(b[0]), "r"(b[1]));
}

// ---------------- tf32x3 GEMM: C[M,N] = A[M,K] * B[K,N] --------------------
// Block 128x128, BK=32, 256 threads (8 warps as 2x4), warp tile 64x32.
// A and B are split into tf32 hi+lo in smem; D += Ah*Bh + Ah*Bl + Al*Bh
// recovers ~fp32 precision on the tensor pipe.
#define AS 36    // A smem row stride (BK + 4)
#define BS 132   // B smem row stride (BN + 4)
#define GEMM_SMEM ((128 * AS * 2 + 32 * BS * 2) * 4)

__global__ __launch_bounds__(256) void sgemm_tf32x3(const float* __restrict__ A,
                                                    const float* __restrict__ B,
                                                    float* __restrict__ C,
                                                    int M, int N, int K)
{
    extern __shared__ float sm[];
    float* Ah = sm;                  // [128][AS]
    float* Al = Ah + 128 * AS;
    float* Bh = Al + 128 * AS;       // [32][BS]
    float* Bl = Bh + 32 * BS;

    const int tid  = threadIdx.x;
    const int warp = tid >> 5;
    const int lane = tid & 31;
    const int g    = lane >> 2;      // 0..7
    const int t    = lane & 3;       // 0..3
    const int wm   = warp >> 2;      // 0..1
    const int wn   = warp & 3;       // 0..3
    const int bx   = blockIdx.x * 128;
    const int by   = blockIdx.y * 128;

    float d[4][4][4] = {};

    for (int k0 = 0; k0 < K; k0 += 32) {
        // ---- stage A tile 128x32 (hi/lo) ----
#pragma unroll
        for (int i = 0; i < 4; i++) {
            int v = tid + i * 256;
            int r = v >> 3, c = (v & 7) * 4;
            float4 x = *(const float4*)(A + (long)(by + r) * K + k0 + c);
            float4 h, l;
            h.x = to_tf32(x.x); l.x = to_tf32(x.x - h.x);
            h.y = to_tf32(x.y); l.y = to_tf32(x.y - h.y);
            h.z = to_tf32(x.z); l.z = to_tf32(x.z - h.z);
            h.w = to_tf32(x.w); l.w = to_tf32(x.w - h.w);
            *(float4*)&Ah[r * AS + c] = h;
            *(float4*)&Al[r * AS + c] = l;
        }
        // ---- stage B tile 32x128 (hi/lo) ----
#pragma unroll
        for (int i = 0; i < 4; i++) {
            int v = tid + i * 256;
            int r = v >> 5, c = (v & 31) * 4;
            float4 x = *(const float4*)(B + (long)(k0 + r) * N + bx + c);
            float4 h, l;
            h.x = to_tf32(x.x); l.x = to_tf32(x.x - h.x);
            h.y = to_tf32(x.y); l.y = to_tf32(x.y - h.y);
            h.z = to_tf32(x.z); l.z = to_tf32(x.z - h.z);
            h.w = to_tf32(x.w); l.w = to_tf32(x.w - h.w);
            *(float4*)&Bh[r * BS + c] = h;
            *(float4*)&Bl[r * BS + c] = l;
        }
        __syncthreads();

#pragma unroll
        for (int ks = 0; ks < 4; ks++) {
            const int kb = ks * 8;
            uint32_t ah[4][4], al[4][4], bh[4][2], bl[4][2];
#pragma unroll
            for (int mt = 0; mt < 4; mt++) {
                int r0 = (wm * 64 + mt * 16 + g) * AS + kb + t;
                ah[mt][0] = __float_as_uint(Ah[r0]);
                ah[mt][1] = __float_as_uint(Ah[r0 + 8 * AS]);
                ah[mt][2] = __float_as_uint(Ah[r0 + 4]);
                ah[mt][3] = __float_as_uint(Ah[r0 + 8 * AS + 4]);
                al[mt][0] = __float_as_uint(Al[r0]);
                al[mt][1] = __float_as_uint(Al[r0 + 8 * AS]);
                al[mt][2] = __float_as_uint(Al[r0 + 4]);
                al[mt][3] = __float_as_uint(Al[r0 + 8 * AS + 4]);
            }
#pragma unroll
            for (int nt = 0; nt < 4; nt++) {
                int c0 = (kb + t) * BS + wn * 32 + nt * 8 + g;
                bh[nt][0] = __float_as_uint(Bh[c0]);
                bh[nt][1] = __float_as_uint(Bh[c0 + 4 * BS]);
                bl[nt][0] = __float_as_uint(Bl[c0]);
                bl[nt][1] = __float_as_uint(Bl[c0 + 4 * BS]);
            }
#pragma unroll
            for (int mt = 0; mt < 4; mt++)
#pragma unroll
                for (int nt = 0; nt < 4; nt++) {
                    mma_tf32(d[mt][nt], ah[mt], bh[nt]);
                    mma_tf32(d[mt][nt], ah[mt], bl[nt]);
                    mma_tf32(d[mt][nt], al[mt], bh[nt]);
                }
        }
        __syncthreads();
    }

    // ---- epilogue ----
#pragma unroll
    for (int mt = 0; mt < 4; mt++)
#pragma unroll
        for (int nt = 0; nt < 4; nt++) {
            int row = by + wm * 64 + mt * 16 + g;
            int col = bx + wn * 32 + nt * 8 + t * 2;
            float2 v0 = make_float2(d[mt][nt][0], d[mt][nt][1]);
            float2 v1 = make_float2(d[mt][nt][2], d[mt][nt][3]);
            *(float2*)(C + (long)row * N + col)       = v0;
            *(float2*)(C + (long)(row + 8) * N + col) = v1;
        }
}

// ---------------- fused per-head RMSNorm + RoPE (in place, Q and K) --------
__global__ __launch_bounds__(256) void rms_rope(float* __restrict__ q,
                                                float* __restrict__ k,
                                                const int* __restrict__ pos,
                                                const float* __restrict__ qw,
                                                const float* __restrict__ kw)
{
    const int s    = blockIdx.x;
    const int warp = threadIdx.x >> 5;
    const int lane = threadIdx.x & 31;
    const float p  = (float)pos[s];

    const int d   = lane * 4;
    const int dp0 = lane * 2;
    const float Cf = 9.210340371976184f / 64.0f;
    float f0 = __expf(-(float)dp0 * Cf);
    float f1 = __expf(-(float)(dp0 + 1) * Cf);
    float s0, c0, s1, c1;
    sincosf(p * f0, &s0, &c0);
    sincosf(p * f1, &s1, &c1);

    float4 w_q = *(const float4*)(qw + d);
    float4 w_k = *(const float4*)(kw + d);

    for (int h = warp; h < NH; h += 8) {
        float* base_q = q + ((long)s * NH + h) * HD + d;
        float* base_k = k + ((long)s * NH + h) * HD + d;
#pragma unroll
        for (int which = 0; which < 2; which++) {
            float* ptr = which ? base_k : base_q;
            float4 wv  = which ? w_k : w_q;
            float4 x = *(float4*)ptr;
            float ss = x.x * x.x + x.y * x.y + x.z * x.z + x.w * x.w;
#pragma unroll
            for (int off = 16; off; off >>= 1)
                ss += __shfl_xor_sync(0xffffffffu, ss, off);
            float r = rsqrtf(ss * (1.0f / 128.0f) + 1e-6f);
            x.x *= r * wv.x; x.y *= r * wv.y; x.z *= r * wv.z; x.w *= r * wv.w;
            float o0 = x.x * c0 - x.y * s0;
            float o1 = x.x * s0 + x.y * c0;
            float o2 = x.z * c1 - x.w * s1;
            float o3 = x.z * s1 + x.w * c1;
            *(float4*)ptr = make_float4(o0, o1, o2, o3);
        }
    }
}

// ---------------- flash attention (fp32, non-causal) -----------------------
#define QSTR 132
#define PSTR 68
#define FLASH_SMEM ((3 * 64 * QSTR + 64 * PSTR) * 4)

__global__ __launch_bounds__(256) void flash_attn(const float* __restrict__ Q,
                                                  const float* __restrict__ K,
                                                  const float* __restrict__ V,
                                                  float* __restrict__ O)
{
    extern __shared__ float sm[];
    float* Qs = sm;
    float* Ks = Qs + 64 * QSTR;
    float* Vs = Ks + 64 * QSTR;
    float* Ps = Vs + 64 * QSTR;

    const int tid = threadIdx.x;
    const int tx  = tid & 15;
    const int ty  = tid >> 4;
    const int h   = blockIdx.y;
    const int q0  = blockIdx.x * 64;
    const float scale = 0.08838834764831845f;

    for (int v = tid; v < 64 * 32; v += 256) {
        int r = v >> 5, c = (v & 31) * 4;
        float4 x = *(const float4*)(Q + ((long)(q0 + r) * NH + h) * HD + c);
        x.x *= scale; x.y *= scale; x.z *= scale; x.w *= scale;
        *(float4*)&Qs[r * QSTR + c] = x;
    }

    float acc[4][8] = {};
    float mi[4] = {-1e30f, -1e30f, -1e30f, -1e30f};
    float li[4] = {};

    for (int kt = 0; kt < SEQ; kt += 64) {
        __syncthreads();
        for (int v = tid; v < 64 * 32; v += 256) {
            int r = v >> 5, c = (v & 31) * 4;
            *(float4*)&Ks[r * QSTR + c] =
                *(const float4*)(K + ((long)(kt + r) * NH + h) * HD + c);
            *(float4*)&Vs[r * QSTR + c] =
                *(const float4*)(V + ((long)(kt + r) * NH + h) * HD + c);
        }
        __syncthreads();

        float sc[4][4] = {};
#pragma unroll 4
        for (int d = 0; d < HD; d += 4) {
            float4 q4[4], k4[4];
#pragma unroll
            for (int i = 0; i < 4; i++)
                q4[i] = *(float4*)&Qs[(ty * 4 + i) * QSTR + d];
#pragma unroll
            for (int j = 0; j < 4; j++)
                k4[j] = *(float4*)&Ks[(tx * 4 + j) * QSTR + d];
#pragma unroll
            for (int i = 0; i < 4; i++)
#pragma unroll
                for (int j = 0; j < 4; j++) {
                    sc[i][j] = fmaf(q4[i].x, k4[j].x, sc[i][j]);
                    sc[i][j] = fmaf(q4[i].y, k4[j].y, sc[i][j]);
                    sc[i][j] = fmaf(q4[i].z, k4[j].z, sc[i][j]);
                    sc[i][j] = fmaf(q4[i].w, k4[j].w, sc[i][j]);
                }
        }

        float mnew[4], alpha[4];
#pragma unroll
        for (int i = 0; i < 4; i++) {
            float rm = fmaxf(fmaxf(sc[i][0], sc[i][1]), fmaxf(sc[i][2], sc[i][3]));
#pragma unroll
            for (int off = 8; off; off >>= 1)
                rm = fmaxf(rm, __shfl_xor_sync(0xffffffffu, rm, off));
            mnew[i]  = fmaxf(mi[i], rm);
            alpha[i] = __expf(mi[i] - mnew[i]);
            mi[i]    = mnew[i];
        }
#pragma unroll
        for (int i = 0; i < 4; i++) {
            float rs = 0.f;
#pragma unroll
            for (int j = 0; j < 4; j++) {
                float pv = __expf(sc[i][j] - mnew[i]);
                Ps[(ty * 4 + i) * PSTR + tx * 4 + j] = pv;
                rs += pv;
            }
#pragma unroll
            for (int off = 8; off; off >>= 1)
                rs += __shfl_xor_sync(0xffffffffu, rs, off);
            li[i] = li[i] * alpha[i] + rs;
#pragma unroll
            for (int jd = 0; jd < 8; jd++) acc[i][jd] *= alpha[i];
        }
        __syncthreads();

#pragma unroll 4
        for (int kc = 0; kc < 64; kc++) {
            float pr[4];
#pragma unroll
            for (int i = 0; i < 4; i++) pr[i] = Ps[(ty * 4 + i) * PSTR + kc];
            float4 v0 = *(float4*)&Vs[kc * QSTR + tx * 8];
            float4 v1 = *(float4*)&Vs[kc * QSTR + tx * 8 + 4];
#pragma unroll
            for (int i = 0; i < 4; i++) {
                acc[i][0] = fmaf(pr[i], v0.x, acc[i][0]);
                acc[i][1] = fmaf(pr[i], v0.y, acc[i][1]);
                acc[i][2] = fmaf(pr[i], v0.z, acc[i][2]);
                acc[i][3] = fmaf(pr[i], v0.w, acc[i][3]);
                acc[i][4] = fmaf(pr[i], v1.x, acc[i][4]);
                acc[i][5] = fmaf(pr[i], v1.y, acc[i][5]);
                acc[i][6] = fmaf(pr[i], v1.z, acc[i][6]);
                acc[i][7] = fmaf(pr[i], v1.w, acc[i][7]);
            }
        }
    }

#pragma unroll
    for (int i = 0; i < 4; i++) {
        float inv = 1.0f / li[i];
        int row = q0 + ty * 4 + i;
        float* op = O + ((long)row * NH + h) * HD + tx * 8;
        float4 o0 = make_float4(acc[i][0] * inv, acc[i][1] * inv,
                                acc[i][2] * inv, acc[i][3] * inv);
        float4 o1 = make_float4(acc[i][4] * inv, acc[i][5] * inv,
                                acc[i][6] * inv, acc[i][7] * inv);
        *(float4*)op       = o0;
        *(float4*)(op + 4) = o1;
    }
}

// ---------------- launch ---------------------------------------------------
extern "C" void kernel_launch(void* const* d_in, const int* in_sizes, int n_in,
                              void* d_out, int out_size)
{
    const float* x   = (const float*)d_in[0];
    const int*   pos = (const int*)d_in[1];
    const float* wq  = (const float*)d_in[2];
    const float* wk  = (const float*)d_in[3];
    const float* wv  = (const float*)d_in[4];
    const float* wo  = (const float*)d_in[5];
    const float* qnw = (const float*)d_in[6];
    const float* knw = (const float*)d_in[7];
    float* out = (float*)d_out;

    float *q, *k, *v, *ctx;
    cudaGetSymbolAddress((void**)&q,   g_q);
    cudaGetSymbolAddress((void**)&k,   g_k);
    cudaGetSymbolAddress((void**)&v,   g_v);
    cudaGetSymbolAddress((void**)&ctx, g_ctx);

    cudaFuncSetAttribute(flash_attn,
                         cudaFuncAttributeMaxDynamicSharedMemorySize,
                         FLASH_SMEM);
    cudaFuncSetAttribute(sgemm_tf32x3,
                         cudaFuncAttributeMaxDynamicSharedMemorySize,
                         GEMM_SMEM);

    dim3 gemm_grid(HID / 128, SEQ / 128);
    sgemm_tf32x3<<<gemm_grid, 256, GEMM_SMEM>>>(x, wq, q, SEQ, HID, HID);
    sgemm_tf32x3<<<gemm_grid, 256, GEMM_SMEM>>>(x, wk, k, SEQ, HID, HID);
    sgemm_tf32x3<<<gemm_grid, 256, GEMM_SMEM>>>(x, wv, v, SEQ, HID, HID);

    rms_rope<<<SEQ, 256>>>(q, k, pos, qnw, knw);

    flash_attn<<<dim3(SEQ / 64, NH), 256, FLASH_SMEM>>>(q, k, v, ctx);

    sgemm_tf32x3<<<gemm_grid, 256, GEMM_SMEM>>>(ctx, wo, out, SEQ, HID, HID);
}

// round 4
// speedup vs baseline: 4.2955x; 4.0118x over previous
#include <cuda_runtime.h>
#include <cuda_bf16.h>
#include <stdint.h>
#include <math.h>

#define SEQ 4096
#define HID 2048
#define NH  16
#define HD  128

// ---------------- scratch (device globals; no allocation allowed) ----------
__device__ float g_q[SEQ * HID];
__device__ float g_k[SEQ * HID];
__device__ float g_v[SEQ * HID];
__device__ float g_ctx[SEQ * HID];
__device__ __nv_bfloat16 g_xh[SEQ * HID];   // activation hi
__device__ __nv_bfloat16 g_xl[SEQ * HID];   // activation lo
__device__ __nv_bfloat16 g_wh[HID * HID];   // weight^T hi  [N][K]
__device__ __nv_bfloat16 g_wl[HID * HID];   // weight^T lo  [N][K]

// ---------------- helpers ---------------------------------------------------
__device__ __forceinline__ uint32_t smem_u32(const void* p) {
    uint32_t a;
    asm("{ .reg .u64 t; cvta.to.shared.u64 t, %1; cvt.u32.u64 %0, t; }"
        : "=r"(a) : "l"(p));
    return a;
}
__device__ __forceinline__ void mma_bf16(float c[4], const uint32_t a[4],
                                         const uint32_t b[2]) {
    asm volatile(
        "mma.sync.aligned.m16n8k16.row.col.f32.bf16.bf16.f32 "
        "{%0,%1,%2,%3},{%4,%5,%6,%7},{%8,%9},{%0,%1,%2,%3};"
        : "+f"(c[0]), "+f"(c[1]), "+f"(c[2]), "+f"(c[3])
        : "r"(a[0]), "r"(a[1]), "r"(a[2]), "r"(a[3]), "r"(b[0]), "r"(b[1]));
}
__device__ __forceinline__ void ldsm4(uint32_t r[4], uint32_t addr) {
    asm volatile("ldmatrix.sync.aligned.m8n8.x4.shared.b16 {%0,%1,%2,%3}, [%4];"
                 : "=r"(r[0]), "=r"(r[1]), "=r"(r[2]), "=r"(r[3]) : "r"(addr));
}
__device__ __forceinline__ void ldsm4t(uint32_t r[4], uint32_t addr) {
    asm volatile(
        "ldmatrix.sync.aligned.m8n8.x4.trans.shared.b16 {%0,%1,%2,%3}, [%4];"
        : "=r"(r[0]), "=r"(r[1]), "=r"(r[2]), "=r"(r[3]) : "r"(addr));
}
// split pair of floats into packed bf16 hi + lo
__device__ __forceinline__ void split2(float x, float y, uint32_t& h, uint32_t& l) {
    __nv_bfloat162 hb = __floats2bfloat162_rn(x, y);
    float hx = __bfloat162float(hb.x), hy = __bfloat162float(hb.y);
    __nv_bfloat162 lb = __floats2bfloat162_rn(x - hx, y - hy);
    h = *(uint32_t*)&hb;
    l = *(uint32_t*)&lb;
}

// ---------------- convert: fp32 rows -> bf16 hi/lo --------------------------
__global__ __launch_bounds__(256) void conv_rows(const float* __restrict__ x,
                                                 __nv_bfloat16* __restrict__ h,
                                                 __nv_bfloat16* __restrict__ l,
                                                 int n)
{
    int i = (blockIdx.x * 256 + threadIdx.x) * 4;
    if (i >= n) return;
    float4 v = *(const float4*)(x + i);
    uint32_t h0, l0, h1, l1;
    split2(v.x, v.y, h0, l0);
    split2(v.z, v.w, h1, l1);
    *(uint2*)(h + i) = make_uint2(h0, h1);
    *(uint2*)(l + i) = make_uint2(l0, l1);
}

// ---------------- convert: W[K,N] fp32 -> W^T[N,K] bf16 hi/lo ---------------
__global__ __launch_bounds__(256) void conv_wt(const float* __restrict__ w,
                                               __nv_bfloat16* __restrict__ ht,
                                               __nv_bfloat16* __restrict__ lt)
{
    __shared__ float tile[32][33];
    const int tx = threadIdx.x, ty = threadIdx.y;
    const int n0 = blockIdx.x * 32, k0 = blockIdx.y * 32;
#pragma unroll
    for (int i = 0; i < 4; i++) {
        int k = ty + i * 8;
        tile[k][tx] = w[(size_t)(k0 + k) * HID + n0 + tx];
    }
    __syncthreads();
#pragma unroll
    for (int i = 0; i < 4; i++) {
        int n = ty + i * 8;
        float v = tile[tx][n];
        __nv_bfloat16 hb = __float2bfloat16(v);
        __nv_bfloat16 lb = __float2bfloat16(v - __bfloat162float(hb));
        size_t o = (size_t)(n0 + n) * HID + k0 + tx;
        ht[o] = hb;
        lt[o] = lb;
    }
}

// ---------------- bf16x3 GEMM via mma.sync + ldmatrix -----------------------
// C[M=4096,N=2048] = A[M,K] * B where B^T[N,K] is staged K-major.
// Block 128x128, BK=64, 256 threads = 8 warps (4m x 2n), warp tile 32x64.
#define GAS 72                         // smem row stride (bf16 elems)
#define GEMM_SMEM (4 * 128 * GAS * 2)  // 73728 B

__global__ __launch_bounds__(256) void gemm_bf16(
    const __nv_bfloat16* __restrict__ Ah_g, const __nv_bfloat16* __restrict__ Al_g,
    const __nv_bfloat16* __restrict__ Bh_g, const __nv_bfloat16* __restrict__ Bl_g,
    float* __restrict__ C)
{
    extern __shared__ __nv_bfloat16 sm[];
    __nv_bfloat16* sAh = sm;
    __nv_bfloat16* sAl = sAh + 128 * GAS;
    __nv_bfloat16* sBh = sAl + 128 * GAS;
    __nv_bfloat16* sBl = sBh + 128 * GAS;

    const int tid  = threadIdx.x;
    const int warp = tid >> 5;
    const int lane = tid & 31;
    const int g    = lane >> 2;
    const int t    = lane & 3;
    const int wm   = warp >> 1;      // 0..3
    const int wn   = warp & 1;       // 0..1
    const int bx   = blockIdx.x * 128;   // N
    const int by   = blockIdx.y * 128;   // M

    const uint32_t aBaseH = smem_u32(sAh);
    const uint32_t aBaseL = smem_u32(sAl);
    const uint32_t bBaseH = smem_u32(sBh);
    const uint32_t bBaseL = smem_u32(sBl);

    float acc[2][8][4] = {};

    // ldmatrix lane addressing pieces
    const int mat  = lane >> 3;          // 0..3
    const int arow = (lane & 7) + 8 * (mat & 1);       // A: row uses mat&1
    const int acol8 = 8 * (mat >> 1);                  // A: col uses mat>>1
    const int brow = (lane & 7) + 8 * (mat >> 1);      // B: row uses mat>>1
    const int bcol8 = 8 * (mat & 1);                   // B: col uses mat&1

    for (int k0 = 0; k0 < HID; k0 += 64) {
        // ---- stage 4 tiles (128 x 64 bf16 each) ----
#pragma unroll
        for (int t4 = 0; t4 < 4; t4++) {
            const __nv_bfloat16* src = (t4 == 0) ? Ah_g : (t4 == 1) ? Al_g
                                     : (t4 == 2) ? Bh_g : Bl_g;
            const int rb = (t4 < 2) ? by : bx;
            __nv_bfloat16* dst = sm + t4 * 128 * GAS;
#pragma unroll
            for (int i = 0; i < 4; i++) {
                int v = tid + i * 256;
                int r = v >> 3, cg = v & 7;
                uint4 val = *(const uint4*)(src + (size_t)(rb + r) * HID + k0 + cg * 8);
                *(uint4*)(dst + r * GAS + cg * 8) = val;
            }
        }
        __syncthreads();

#pragma unroll
        for (int kt = 0; kt < 4; kt++) {
            uint32_t a_h[2][4], a_l[2][4];
#pragma unroll
            for (int mt = 0; mt < 2; mt++) {
                uint32_t off = ((wm * 32 + mt * 16 + arow) * GAS + kt * 16 + acol8) * 2;
                ldsm4(a_h[mt], aBaseH + off);
                ldsm4(a_l[mt], aBaseL + off);
            }
            uint32_t b_h[8][2], b_l[8][2];
#pragma unroll
            for (int p = 0; p < 4; p++) {
                uint32_t off = ((wn * 64 + p * 16 + brow) * GAS + kt * 16 + bcol8) * 2;
                uint32_t r4[4];
                ldsm4(r4, bBaseH + off);
                b_h[2 * p][0] = r4[0]; b_h[2 * p][1] = r4[1];
                b_h[2 * p + 1][0] = r4[2]; b_h[2 * p + 1][1] = r4[3];
                ldsm4(r4, bBaseL + off);
                b_l[2 * p][0] = r4[0]; b_l[2 * p][1] = r4[1];
                b_l[2 * p + 1][0] = r4[2]; b_l[2 * p + 1][1] = r4[3];
            }
#pragma unroll
            for (int mt = 0; mt < 2; mt++)
#pragma unroll
                for (int nt = 0; nt < 8; nt++) {
                    mma_bf16(acc[mt][nt], a_h[mt], b_h[nt]);
                    mma_bf16(acc[mt][nt], a_h[mt], b_l[nt]);
                    mma_bf16(acc[mt][nt], a_l[mt], b_h[nt]);
                }
        }
        __syncthreads();
    }

    // ---- epilogue ----
#pragma unroll
    for (int mt = 0; mt < 2; mt++)
#pragma unroll
        for (int nt = 0; nt < 8; nt++) {
            int row = by + wm * 32 + mt * 16 + g;
            int col = bx + wn * 64 + nt * 8 + 2 * t;
            *(float2*)(C + (size_t)row * HID + col) =
                make_float2(acc[mt][nt][0], acc[mt][nt][1]);
            *(float2*)(C + (size_t)(row + 8) * HID + col) =
                make_float2(acc[mt][nt][2], acc[mt][nt][3]);
        }
}

// ---------------- fused per-head RMSNorm + RoPE (in place, Q and K) --------
__global__ __launch_bounds__(256) void rms_rope(float* __restrict__ q,
                                                float* __restrict__ k,
                                                const int* __restrict__ pos,
                                                const float* __restrict__ qw,
                                                const float* __restrict__ kw)
{
    const int s    = blockIdx.x;
    const int warp = threadIdx.x >> 5;
    const int lane = threadIdx.x & 31;
    const float p  = (float)pos[s];

    const int d   = lane * 4;
    const int dp0 = lane * 2;
    const float Cf = 9.210340371976184f / 64.0f;
    float f0 = __expf(-(float)dp0 * Cf);
    float f1 = __expf(-(float)(dp0 + 1) * Cf);
    float s0, c0, s1, c1;
    sincosf(p * f0, &s0, &c0);
    sincosf(p * f1, &s1, &c1);

    float4 w_q = *(const float4*)(qw + d);
    float4 w_k = *(const float4*)(kw + d);

    for (int h = warp; h < NH; h += 8) {
        float* base_q = q + ((size_t)s * NH + h) * HD + d;
        float* base_k = k + ((size_t)s * NH + h) * HD + d;
#pragma unroll
        for (int which = 0; which < 2; which++) {
            float* ptr = which ? base_k : base_q;
            float4 wv  = which ? w_k : w_q;
            float4 x = *(float4*)ptr;
            float ss = x.x * x.x + x.y * x.y + x.z * x.z + x.w * x.w;
#pragma unroll
            for (int off = 16; off; off >>= 1)
                ss += __shfl_xor_sync(0xffffffffu, ss, off);
            float r = rsqrtf(ss * (1.0f / 128.0f) + 1e-6f);
            x.x *= r * wv.x; x.y *= r * wv.y; x.z *= r * wv.z; x.w *= r * wv.w;
            float o0 = x.x * c0 - x.y * s0;
            float o1 = x.x * s0 + x.y * c0;
            float o2 = x.z * c1 - x.w * s1;
            float o3 = x.z * s1 + x.w * c1;
            *(float4*)ptr = make_float4(o0, o1, o2, o3);
        }
    }
}

// ---------------- flash attention via mma.sync bf16x3 ----------------------
// CTA: 128 q rows x full KV (64 per iter). 8 warps, warp = 16 q rows.
#define FS 136   // smem row stride (bf16 elems)
#define FLASH_SMEM ((2 * 128 * FS + 4 * 64 * FS) * 2)   // 139264 B

__global__ __launch_bounds__(256) void flash_mma(const float* __restrict__ Q,
                                                 const float* __restrict__ K,
                                                 const float* __restrict__ V,
                                                 float* __restrict__ O)
{
    extern __shared__ __nv_bfloat16 sm[];
    __nv_bfloat16* sQh = sm;                    // [128][FS]
    __nv_bfloat16* sQl = sQh + 128 * FS;
    __nv_bfloat16* sKh = sQl + 128 * FS;        // [64][FS]
    __nv_bfloat16* sKl = sKh + 64 * FS;
    __nv_bfloat16* sVh = sKl + 64 * FS;
    __nv_bfloat16* sVl = sVh + 64 * FS;

    const int tid  = threadIdx.x;
    const int warp = tid >> 5;
    const int lane = tid & 31;
    const int g    = lane >> 2;
    const int t    = lane & 3;
    const int h    = blockIdx.y;
    const int q0   = blockIdx.x * 128;
    const float scale = 0.08838834764831845f;   // 1/sqrt(128)

    const uint32_t qBaseH = smem_u32(sQh);
    const uint32_t qBaseL = smem_u32(sQl);
    const uint32_t kBaseH = smem_u32(sKh);
    const uint32_t kBaseL = smem_u32(sKl);
    const uint32_t vBaseH = smem_u32(sVh);
    const uint32_t vBaseL = smem_u32(sVl);

    // ---- stage Q (scaled) as bf16 hi/lo ----
#pragma unroll
    for (int i = 0; i < 16; i++) {
        int v = tid + i * 256;
        int r = v >> 5, cg = (v & 31) * 4;
        float4 x = *(const float4*)(Q + (size_t)(q0 + r) * HID + h * HD + cg);
        x.x *= scale; x.y *= scale; x.z *= scale; x.w *= scale;
        uint32_t h0, l0, h1, l1;
        split2(x.x, x.y, h0, l0);
        split2(x.z, x.w, h1, l1);
        *(uint2*)(sQh + r * FS + cg) = make_uint2(h0, h1);
        *(uint2*)(sQl + r * FS + cg) = make_uint2(l0, l1);
    }

    const int wq = warp * 16;
    float o[16][4] = {};
    float m0 = -1e30f, m1 = -1e30f, l0s = 0.f, l1s = 0.f;

    // ldmatrix lane addressing
    const int mat  = lane >> 3;
    const int arow = (lane & 7) + 8 * (mat & 1);
    const int acol8 = 8 * (mat >> 1);
    const int brow = (lane & 7) + 8 * (mat >> 1);
    const int bcol8 = 8 * (mat & 1);
    const int vrow = (lane & 7) + 8 * (mat & 1);   // trans: row uses mat&1
    const int vcol8 = 8 * (mat >> 1);

    for (int kt0 = 0; kt0 < SEQ; kt0 += 64) {
        __syncthreads();
        // ---- stage K, V hi/lo ----
#pragma unroll
        for (int i = 0; i < 8; i++) {
            int v = tid + i * 256;
            int r = v >> 5, cg = (v & 31) * 4;
            size_t goff = (size_t)(kt0 + r) * HID + h * HD + cg;
            float4 xk = *(const float4*)(K + goff);
            uint32_t h0, l0, h1, l1;
            split2(xk.x, xk.y, h0, l0);
            split2(xk.z, xk.w, h1, l1);
            *(uint2*)(sKh + r * FS + cg) = make_uint2(h0, h1);
            *(uint2*)(sKl + r * FS + cg) = make_uint2(l0, l1);
            float4 xv = *(const float4*)(V + goff);
            split2(xv.x, xv.y, h0, l0);
            split2(xv.z, xv.w, h1, l1);
            *(uint2*)(sVh + r * FS + cg) = make_uint2(h0, h1);
            *(uint2*)(sVl + r * FS + cg) = make_uint2(l0, l1);
        }
        __syncthreads();

        // ---- S = Q K^T  (16 x 64 per warp) ----
        float S[8][4] = {};
#pragma unroll
        for (int c = 0; c < 8; c++) {
            uint32_t a_h[4], a_l[4];
            uint32_t aoff = ((wq + arow) * FS + c * 16 + acol8) * 2;
            ldsm4(a_h, qBaseH + aoff);
            ldsm4(a_l, qBaseL + aoff);
#pragma unroll
            for (int p = 0; p < 4; p++) {
                uint32_t boff = ((p * 16 + brow) * FS + c * 16 + bcol8) * 2;
                uint32_t bh4[4], bl4[4];
                ldsm4(bh4, kBaseH + boff);
                ldsm4(bl4, kBaseL + boff);
                uint32_t bh0[2] = {bh4[0], bh4[1]}, bh1[2] = {bh4[2], bh4[3]};
                uint32_t bl0[2] = {bl4[0], bl4[1]}, bl1[2] = {bl4[2], bl4[3]};
                mma_bf16(S[2 * p], a_h, bh0);
                mma_bf16(S[2 * p], a_h, bl0);
                mma_bf16(S[2 * p], a_l, bh0);
                mma_bf16(S[2 * p + 1], a_h, bh1);
                mma_bf16(S[2 * p + 1], a_h, bl1);
                mma_bf16(S[2 * p + 1], a_l, bh1);
            }
        }

        // ---- online softmax (rows g and g+8 of this warp) ----
        float rm0 = -1e30f, rm1 = -1e30f;
#pragma unroll
        for (int nt = 0; nt < 8; nt++) {
            rm0 = fmaxf(rm0, fmaxf(S[nt][0], S[nt][1]));
            rm1 = fmaxf(rm1, fmaxf(S[nt][2], S[nt][3]));
        }
        rm0 = fmaxf(rm0, __shfl_xor_sync(0xffffffffu, rm0, 1));
        rm0 = fmaxf(rm0, __shfl_xor_sync(0xffffffffu, rm0, 2));
        rm1 = fmaxf(rm1, __shfl_xor_sync(0xffffffffu, rm1, 1));
        rm1 = fmaxf(rm1, __shfl_xor_sync(0xffffffffu, rm1, 2));
        float mn0 = fmaxf(m0, rm0), mn1 = fmaxf(m1, rm1);
        float a0 = __expf(m0 - mn0), a1 = __expf(m1 - mn1);
        m0 = mn0; m1 = mn1;

        uint32_t Ph0[8], Ph1[8], Pl0[8], Pl1[8];
        float s0 = 0.f, s1 = 0.f;
#pragma unroll
        for (int nt = 0; nt < 8; nt++) {
            float p00 = __expf(S[nt][0] - mn0);
            float p01 = __expf(S[nt][1] - mn0);
            float p10 = __expf(S[nt][2] - mn1);
            float p11 = __expf(S[nt][3] - mn1);
            s0 += p00 + p01;
            s1 += p10 + p11;
            split2(p00, p01, Ph0[nt], Pl0[nt]);
            split2(p10, p11, Ph1[nt], Pl1[nt]);
        }
        s0 += __shfl_xor_sync(0xffffffffu, s0, 1);
        s0 += __shfl_xor_sync(0xffffffffu, s0, 2);
        s1 += __shfl_xor_sync(0xffffffffu, s1, 1);
        s1 += __shfl_xor_sync(0xffffffffu, s1, 2);
        l0s = l0s * a0 + s0;
        l1s = l1s * a1 + s1;
#pragma unroll
        for (int d = 0; d < 16; d++) {
            o[d][0] *= a0; o[d][1] *= a0;
            o[d][2] *= a1; o[d][3] *= a1;
        }

        // ---- O += P V  (k over kv in 4 tiles of 16, n over d in 16 tiles) ----
#pragma unroll
        for (int c = 0; c < 4; c++) {
            uint32_t A_h[4] = {Ph0[2 * c], Ph1[2 * c], Ph0[2 * c + 1], Ph1[2 * c + 1]};
            uint32_t A_l[4] = {Pl0[2 * c], Pl1[2 * c], Pl0[2 * c + 1], Pl1[2 * c + 1]};
#pragma unroll
            for (int dd = 0; dd < 8; dd++) {
                uint32_t voff = ((c * 16 + vrow) * FS + dd * 16 + vcol8) * 2;
                uint32_t vh4[4], vl4[4];
                ldsm4t(vh4, vBaseH + voff);
                ldsm4t(vl4, vBaseL + voff);
                uint32_t vh0[2] = {vh4[0], vh4[1]}, vh1[2] = {vh4[2], vh4[3]};
                uint32_t vl0[2] = {vl4[0], vl4[1]}, vl1[2] = {vl4[2], vl4[3]};
                mma_bf16(o[2 * dd], A_h, vh0);
                mma_bf16(o[2 * dd], A_h, vl0);
                mma_bf16(o[2 * dd], A_l, vh0);
                mma_bf16(o[2 * dd + 1], A_h, vh1);
                mma_bf16(o[2 * dd + 1], A_h, vl1);
                mma_bf16(o[2 * dd + 1], A_l, vh1);
            }
        }
    }

    // ---- epilogue ----
    float inv0 = 1.0f / l0s, inv1 = 1.0f / l1s;
    int row0 = q0 + wq + g;
#pragma unroll
    for (int d = 0; d < 16; d++) {
        int col = h * HD + d * 8 + 2 * t;
        *(float2*)(O + (size_t)row0 * HID + col) =
            make_float2(o[d][0] * inv0, o[d][1] * inv0);
        *(float2*)(O + (size_t)(row0 + 8) * HID + col) =
            make_float2(o[d][2] * inv1, o[d][3] * inv1);
    }
}

// ---------------- launch ---------------------------------------------------
extern "C" void kernel_launch(void* const* d_in, const int* in_sizes, int n_in,
                              void* d_out, int out_size)
{
    const float* x   = (const float*)d_in[0];
    const int*   pos = (const int*)d_in[1];
    const float* wq  = (const float*)d_in[2];
    const float* wk  = (const float*)d_in[3];
    const float* wv  = (const float*)d_in[4];
    const float* wo  = (const float*)d_in[5];
    const float* qnw = (const float*)d_in[6];
    const float* knw = (const float*)d_in[7];
    float* out = (float*)d_out;

    float *q, *k, *v, *ctx;
    __nv_bfloat16 *xh, *xl, *wh, *wl;
    cudaGetSymbolAddress((void**)&q,   g_q);
    cudaGetSymbolAddress((void**)&k,   g_k);
    cudaGetSymbolAddress((void**)&v,   g_v);
    cudaGetSymbolAddress((void**)&ctx, g_ctx);
    cudaGetSymbolAddress((void**)&xh,  g_xh);
    cudaGetSymbolAddress((void**)&xl,  g_xl);
    cudaGetSymbolAddress((void**)&wh,  g_wh);
    cudaGetSymbolAddress((void**)&wl,  g_wl);

    cudaFuncSetAttribute(gemm_bf16,
                         cudaFuncAttributeMaxDynamicSharedMemorySize, GEMM_SMEM);
    cudaFuncSetAttribute(flash_mma,
                         cudaFuncAttributeMaxDynamicSharedMemorySize, FLASH_SMEM);

    const int NELEM = SEQ * HID;
    dim3 cw_grid(HID / 32, HID / 32), cw_blk(32, 8);
    dim3 gg(HID / 128, SEQ / 128);

    conv_rows<<<NELEM / 1024, 256>>>(x, xh, xl, NELEM);

    conv_wt<<<cw_grid, cw_blk>>>(wq, wh, wl);
    gemm_bf16<<<gg, 256, GEMM_SMEM>>>(xh, xl, wh, wl, q);

    conv_wt<<<cw_grid, cw_blk>>>(wk, wh, wl);
    gemm_bf16<<<gg, 256, GEMM_SMEM>>>(xh, xl, wh, wl, k);

    conv_wt<<<cw_grid, cw_blk>>>(wv, wh, wl);
    gemm_bf16<<<gg, 256, GEMM_SMEM>>>(xh, xl, wh, wl, v);

    rms_rope<<<SEQ, 256>>>(q, k, pos, qnw, knw);

    flash_mma<<<dim3(SEQ / 128, NH), 256, FLASH_SMEM>>>(q, k, v, ctx);

    conv_rows<<<NELEM / 1024, 256>>>(ctx, xh, xl, NELEM);
    conv_wt<<<cw_grid, cw_blk>>>(wo, wh, wl);
    gemm_bf16<<<gg, 256, GEMM_SMEM>>>(xh, xl, wh, wl, out);
}